// round 1
// baseline (speedup 1.0000x reference)
#include <cuda_runtime.h>
#include <math.h>

#define S_LEN   2048
#define BATCH   2
#define DMODEL  1024
#define NHEADS  16
#define DHEAD   64
#define MROWS   (BATCH * S_LEN)   // 4096
#define IGNORE_VAL (-100000.0f)

// ---------------- scratch (no allocations allowed) ----------------
__device__ float g_wqt[DMODEL * DMODEL];
__device__ float g_wkt[DMODEL * DMODEL];
__device__ float g_wvt[DMODEL * DMODEL];
__device__ float g_q[MROWS * DMODEL];
__device__ float g_k[MROWS * DMODEL];
__device__ float g_v[MROWS * DMODEL];
__device__ float g_z[MROWS * DMODEL];

// ---------------- weight transpose: [H, M, D] -> [M, H*D] ----------------
__global__ void transpose_w(const float* __restrict__ w, float* __restrict__ wt) {
    int idx = blockIdx.x * 256 + threadIdx.x;       // over 1024*1024
    int n = idx & (DMODEL - 1);
    int m = idx >> 10;
    int h = n >> 6;
    int d = n & 63;
    wt[idx] = w[h * (DMODEL * DHEAD) + m * DHEAD + d];
}

// ---------------- tiled fp32 SGEMM: C[M,N] = A[M,K] * B[K,N] (+bias[N]) ----------------
// 128x128 block tile, K-step 8, 256 threads, 8x8 per thread.
__global__ __launch_bounds__(256) void sgemm128(
    const float* __restrict__ A, const float* __restrict__ B,
    const float* __restrict__ bias, float* __restrict__ C,
    int M, int N, int K)
{
    __shared__ float As[8][128];
    __shared__ float Bs[8][128];

    int tid = threadIdx.x;
    int tx = tid & 15;
    int ty = tid >> 4;

    const float* Ap = A + (size_t)blockIdx.y * 128 * K;
    const float* Bp = B + blockIdx.x * 128;

    float acc[8][8];
#pragma unroll
    for (int i = 0; i < 8; i++)
#pragma unroll
        for (int j = 0; j < 8; j++) acc[i][j] = 0.0f;

    int arow = tid >> 1, acol = (tid & 1) * 4;
    int brow = tid >> 5, bcol = (tid & 31) * 4;

    for (int k0 = 0; k0 < K; k0 += 8) {
        float4 a4 = *(const float4*)(Ap + (size_t)arow * K + k0 + acol);
        As[acol + 0][arow] = a4.x;
        As[acol + 1][arow] = a4.y;
        As[acol + 2][arow] = a4.z;
        As[acol + 3][arow] = a4.w;
        *(float4*)(&Bs[brow][bcol]) =
            *(const float4*)(Bp + (size_t)(k0 + brow) * N + bcol);
        __syncthreads();

#pragma unroll
        for (int k = 0; k < 8; k++) {
            float ar[8], br[8];
#pragma unroll
            for (int i = 0; i < 8; i++) ar[i] = As[k][ty * 8 + i];
#pragma unroll
            for (int j = 0; j < 8; j++) br[j] = Bs[k][tx * 8 + j];
#pragma unroll
            for (int i = 0; i < 8; i++)
#pragma unroll
                for (int j = 0; j < 8; j++) acc[i][j] += ar[i] * br[j];
        }
        __syncthreads();
    }

#pragma unroll
    for (int i = 0; i < 8; i++) {
        int row = blockIdx.y * 128 + ty * 8 + i;
#pragma unroll
        for (int j = 0; j < 8; j += 4) {
            int col = blockIdx.x * 128 + tx * 8 + j;
            float4 v;
            v.x = acc[i][j + 0] + (bias ? bias[col + 0] : 0.0f);
            v.y = acc[i][j + 1] + (bias ? bias[col + 1] : 0.0f);
            v.z = acc[i][j + 2] + (bias ? bias[col + 2] : 0.0f);
            v.w = acc[i][j + 3] + (bias ? bias[col + 3] : 0.0f);
            *(float4*)(C + (size_t)row * N + col) = v;
        }
    }
}

// ---------------- flash attention (causal + additive mask) ----------------
// grid: (S/64, NHEADS, BATCH), block: 256 threads.
// Q tile 64 rows, K/V tiles 64 rows. Per-thread 4x4 micro-tile.
#define FL_LDS 68   // 64 + 4 pad (keeps float4 alignment)

__global__ __launch_bounds__(256) void flash_attn(
    const float* __restrict__ q, const float* __restrict__ k,
    const float* __restrict__ v, const float* __restrict__ amask,
    float* __restrict__ z)
{
    extern __shared__ float sm[];
    float* Qs = sm;                   // 64 * FL_LDS
    float* Ks = sm + 64 * FL_LDS;
    float* Vs = sm + 2 * 64 * FL_LDS;
    float* Ps = sm + 3 * 64 * FL_LDS;

    const int qt = blockIdx.x;
    const int h  = blockIdx.y;
    const int b  = blockIdx.z;
    const int tid = threadIdx.x;
    const int tx = tid & 15;
    const int ty = tid >> 4;
    const int i0 = ty * 4;            // local q rows
    const int j0 = tx * 4;            // local k cols (score tile)
    const int d0 = tx * 4;            // local d cols (output tile)

    const size_t baseRow = (size_t)b * S_LEN;
    const int lr = tid >> 4;          // loader row (0..15)
    const int lc = tid & 15;          // loader float4 col (0..15)

    // load Q tile
#pragma unroll
    for (int rr = 0; rr < 64; rr += 16) {
        int row = lr + rr;
        *(float4*)(Qs + row * FL_LDS + lc * 4) =
            *(const float4*)(q + (baseRow + qt * 64 + row) * DMODEL + h * 64 + lc * 4);
    }

    float m_prev[4], l_sum[4], o[4][4];
#pragma unroll
    for (int r = 0; r < 4; r++) {
        m_prev[r] = -1e30f;
        l_sum[r] = 0.0f;
#pragma unroll
        for (int c = 0; c < 4; c++) o[r][c] = 0.0f;
    }

    for (int kt = 0; kt <= qt; kt++) {
        __syncthreads();   // prior-iter reads of Ks/Vs/Ps done; Qs visible on first iter
#pragma unroll
        for (int rr = 0; rr < 64; rr += 16) {
            int row = lr + rr;
            *(float4*)(Ks + row * FL_LDS + lc * 4) =
                *(const float4*)(k + (baseRow + kt * 64 + row) * DMODEL + h * 64 + lc * 4);
            *(float4*)(Vs + row * FL_LDS + lc * 4) =
                *(const float4*)(v + (baseRow + kt * 64 + row) * DMODEL + h * 64 + lc * 4);
        }
        __syncthreads();

        // S = Q K^T  (4x4 per thread)
        float sacc[4][4];
#pragma unroll
        for (int r = 0; r < 4; r++)
#pragma unroll
            for (int c = 0; c < 4; c++) sacc[r][c] = 0.0f;

        for (int d = 0; d < 64; d += 4) {
            float4 qr[4], kr[4];
#pragma unroll
            for (int r = 0; r < 4; r++) qr[r] = *(float4*)(Qs + (i0 + r) * FL_LDS + d);
#pragma unroll
            for (int c = 0; c < 4; c++) kr[c] = *(float4*)(Ks + (j0 + c) * FL_LDS + d);
#pragma unroll
            for (int r = 0; r < 4; r++)
#pragma unroll
                for (int c = 0; c < 4; c++)
                    sacc[r][c] += qr[r].x * kr[c].x + qr[r].y * kr[c].y +
                                  qr[r].z * kr[c].z + qr[r].w * kr[c].w;
        }

        // scale, causal mask, additive mask (reference: where(causal, s, IGNORE) + mask)
#pragma unroll
        for (int r = 0; r < 4; r++) {
            int qi = qt * 64 + i0 + r;
#pragma unroll
            for (int c = 0; c < 4; c++) {
                int kj = kt * 64 + j0 + c;
                float s = (kj <= qi) ? sacc[r][c] * 0.125f : IGNORE_VAL;
                s += amask[b * S_LEN + kj];
                sacc[r][c] = s;
            }
        }

        // row max (across 16 lanes of same row strip)
        float tm[4];
#pragma unroll
        for (int r = 0; r < 4; r++) {
            float mx = fmaxf(fmaxf(sacc[r][0], sacc[r][1]), fmaxf(sacc[r][2], sacc[r][3]));
#pragma unroll
            for (int msk = 1; msk < 16; msk <<= 1)
                mx = fmaxf(mx, __shfl_xor_sync(0xffffffffu, mx, msk));
            tm[r] = mx;
        }

        // online softmax update
#pragma unroll
        for (int r = 0; r < 4; r++) {
            float mn = fmaxf(m_prev[r], tm[r]);
            float alpha = __expf(m_prev[r] - mn);
            float rsum = 0.0f;
#pragma unroll
            for (int c = 0; c < 4; c++) {
                float p = __expf(sacc[r][c] - mn);
                sacc[r][c] = p;
                rsum += p;
            }
#pragma unroll
            for (int msk = 1; msk < 16; msk <<= 1)
                rsum += __shfl_xor_sync(0xffffffffu, rsum, msk);
            l_sum[r] = l_sum[r] * alpha + rsum;
            m_prev[r] = mn;
#pragma unroll
            for (int c = 0; c < 4; c++) o[r][c] *= alpha;
        }

        // stage P
#pragma unroll
        for (int r = 0; r < 4; r++)
#pragma unroll
            for (int c = 0; c < 4; c++)
                Ps[(i0 + r) * FL_LDS + j0 + c] = sacc[r][c];
        __syncthreads();

        // O += P * V
        for (int j = 0; j < 64; j++) {
            float4 vv = *(float4*)(Vs + j * FL_LDS + d0);
#pragma unroll
            for (int r = 0; r < 4; r++) {
                float p = Ps[(i0 + r) * FL_LDS + j];
                o[r][0] += p * vv.x;
                o[r][1] += p * vv.y;
                o[r][2] += p * vv.z;
                o[r][3] += p * vv.w;
            }
        }
    }

    // write z = O / l
#pragma unroll
    for (int r = 0; r < 4; r++) {
        float inv = 1.0f / l_sum[r];
        int row = qt * 64 + i0 + r;
        float4 outv;
        outv.x = o[r][0] * inv;
        outv.y = o[r][1] * inv;
        outv.z = o[r][2] * inv;
        outv.w = o[r][3] * inv;
        *(float4*)(z + (baseRow + row) * DMODEL + h * 64 + d0) = outv;
    }
}

// ---------------- launch ----------------
extern "C" void kernel_launch(void* const* d_in, const int* in_sizes, int n_in,
                              void* d_out, int out_size)
{
    const float* x_q  = (const float*)d_in[0];
    const float* x_k  = (const float*)d_in[1];
    const float* x_v  = (const float*)d_in[2];
    const float* amsk = (const float*)d_in[3];
    const float* w_q  = (const float*)d_in[4];
    const float* w_k  = (const float*)d_in[5];
    const float* w_v  = (const float*)d_in[6];
    const float* w_o  = (const float*)d_in[7];
    const float* b_q  = (const float*)d_in[8];
    const float* b_k  = (const float*)d_in[9];
    const float* b_v  = (const float*)d_in[10];
    const float* b_o  = (const float*)d_in[11];
    float* out = (float*)d_out;

    float *gwqt, *gwkt, *gwvt, *gq, *gk, *gv, *gz;
    cudaGetSymbolAddress((void**)&gwqt, g_wqt);
    cudaGetSymbolAddress((void**)&gwkt, g_wkt);
    cudaGetSymbolAddress((void**)&gwvt, g_wvt);
    cudaGetSymbolAddress((void**)&gq,   g_q);
    cudaGetSymbolAddress((void**)&gk,   g_k);
    cudaGetSymbolAddress((void**)&gv,   g_v);
    cudaGetSymbolAddress((void**)&gz,   g_z);

    // opt-in dynamic smem for flash kernel (69,632 B)
    static int smem_set = 0;
    int fl_smem = 4 * 64 * FL_LDS * sizeof(float);
    cudaFuncSetAttribute(flash_attn, cudaFuncAttributeMaxDynamicSharedMemorySize, fl_smem);

    // 1. transpose QKV weights into [K, N] row-major
    transpose_w<<<(DMODEL * DMODEL) / 256, 256>>>(w_q, gwqt);
    transpose_w<<<(DMODEL * DMODEL) / 256, 256>>>(w_k, gwkt);
    transpose_w<<<(DMODEL * DMODEL) / 256, 256>>>(w_v, gwvt);

    // 2. QKV projections
    dim3 ggrid(DMODEL / 128, MROWS / 128);
    sgemm128<<<ggrid, 256>>>(x_q, gwqt, b_q, gq, MROWS, DMODEL, DMODEL);
    sgemm128<<<ggrid, 256>>>(x_k, gwkt, b_k, gk, MROWS, DMODEL, DMODEL);
    sgemm128<<<ggrid, 256>>>(x_v, gwvt, b_v, gv, MROWS, DMODEL, DMODEL);

    // 3. flash attention
    dim3 fgrid(S_LEN / 64, NHEADS, BATCH);
    flash_attn<<<fgrid, 256, fl_smem>>>(gq, gk, gv, amsk, gz);

    // 4. output projection (W_O is already [h*64+d, m] row-major)
    sgemm128<<<ggrid, 256>>>(gz, w_o, b_o, out, MROWS, DMODEL, DMODEL);

    (void)in_sizes; (void)n_in; (void)out_size; (void)smem_set;
}